// round 8
// baseline (speedup 1.0000x reference)
#include <cuda_runtime.h>
#include <cuda_fp16.h>
#include <cstdint>

// Problem constants
#define B_    2
#define S_    2048
#define E_    2048
#define H_    32
#define KH_   8
#define HD_   64
#define F_    8192
#define KV_   (KH_*HD_)      // 512
#define QKVN  (E_ + 2*KV_)   // 3072
#define M_    (B_*S_)        // 4096

// -------- scratch (device globals: allocation-free) --------
__device__ __half g_wqkvh[(size_t)QKVN*E_];
__device__ __half g_woh  [(size_t)E_*E_];
__device__ __half g_w13h [(size_t)2*F_*E_];
__device__ __half g_w2h  [(size_t)E_*F_];

__device__ __half g_h    [(size_t)M_*E_];
__device__ __half g_qkvh [(size_t)M_*QKVN];
__device__ __half g_qh   [(size_t)B_*H_ *S_*HD_];
__device__ __half g_kh   [(size_t)B_*KH_*S_*HD_];
__device__ __half g_vh   [(size_t)B_*KH_*S_*HD_];
__device__ __half g_o    [(size_t)M_*E_];
__device__ float  g_h2   [(size_t)M_*E_];
__device__ __half g_g    [(size_t)M_*E_];
__device__ __half g_c13  [(size_t)M_*2*F_];
__device__ __half g_act  [(size_t)M_*F_];

__device__ __forceinline__ uint32_t smem_u32(const void* p) {
    uint32_t a;
    asm("{ .reg .u64 t; cvta.to.shared.u64 t, %1; cvt.u32.u64 %0, t; }" : "=r"(a) : "l"(p));
    return a;
}
__device__ __forceinline__ uint32_t packh2(float a, float b) {
    __half2 h = __floats2half2_rn(a, b);
    return *reinterpret_cast<uint32_t*>(&h);
}
__device__ __forceinline__ float2 unpackh2(uint32_t u) {
    __half2 h = *reinterpret_cast<__half2*>(&u);
    return __half22float2(h);
}

// ============================================================
// fp32 -> fp16 bulk convert (weights). n % 1024 == 0.
// ============================================================
__global__ __launch_bounds__(256) void f2h_kernel(
    const float* __restrict__ in, __half* __restrict__ out)
{
    const size_t i = ((size_t)blockIdx.x * 256 + threadIdx.x) * 4;
    float4 v = *reinterpret_cast<const float4*>(in + i);
    uint2 o = make_uint2(packh2(v.x, v.y), packh2(v.z, v.w));
    *reinterpret_cast<uint2*>(out + i) = o;
}

// ============================================================
// RMSNorm: fp32 in, fp16 out. one block per row of 2048
// ============================================================
__global__ __launch_bounds__(256) void rmsnorm_kernel(
    const float* __restrict__ x, const float* __restrict__ w, __half* __restrict__ o)
{
    const int tid = threadIdx.x;
    const size_t base = (size_t)blockIdx.x * E_;
    float4 v0 = *reinterpret_cast<const float4*>(x + base + tid*4);
    float4 v1 = *reinterpret_cast<const float4*>(x + base + 1024 + tid*4);
    float ss = v0.x*v0.x + v0.y*v0.y + v0.z*v0.z + v0.w*v0.w
             + v1.x*v1.x + v1.y*v1.y + v1.z*v1.z + v1.w*v1.w;
    #pragma unroll
    for (int off = 16; off; off >>= 1) ss += __shfl_xor_sync(0xffffffffu, ss, off);
    __shared__ float sred[8];
    if ((tid & 31) == 0) sred[tid >> 5] = ss;
    __syncthreads();
    float tot = 0.f;
    #pragma unroll
    for (int i = 0; i < 8; i++) tot += sred[i];
    float inv = rsqrtf(tot * (1.0f / (float)E_) + 1e-5f);
    float4 w0 = *reinterpret_cast<const float4*>(w + tid*4);
    float4 w1 = *reinterpret_cast<const float4*>(w + 1024 + tid*4);
    uint2 o0 = make_uint2(packh2(v0.x*inv*w0.x, v0.y*inv*w0.y),
                          packh2(v0.z*inv*w0.z, v0.w*inv*w0.w));
    uint2 o1 = make_uint2(packh2(v1.x*inv*w1.x, v1.y*inv*w1.y),
                          packh2(v1.z*inv*w1.z, v1.w*inv*w1.w));
    *reinterpret_cast<uint2*>(o + base + tid*4)        = o0;
    *reinterpret_cast<uint2*>(o + base + 1024 + tid*4) = o1;
}

// -------- fp16 mma --------
__device__ __forceinline__ void mma_f16(float* c,
    uint32_t a0, uint32_t a1, uint32_t a2, uint32_t a3,
    uint32_t b0, uint32_t b1)
{
    asm volatile(
        "mma.sync.aligned.m16n8k16.row.col.f32.f16.f16.f32 "
        "{%0,%1,%2,%3}, {%4,%5,%6,%7}, {%8,%9}, {%0,%1,%2,%3};"
        : "+f"(c[0]), "+f"(c[1]), "+f"(c[2]), "+f"(c[3])
        : "r"(a0), "r"(a1), "r"(a2), "r"(a3), "r"(b0), "r"(b1));
}

// interleave two uint4 (halves k0..7, k8..15) into perm slot order
__device__ __forceinline__ void perm_sts(__half* rowp, uint4 lo, uint4 hi) {
    *reinterpret_cast<uint4*>(rowp)     = make_uint4(lo.x, hi.x, lo.y, hi.y);
    *reinterpret_cast<uint4*>(rowp + 8) = make_uint4(lo.z, hi.z, lo.w, hi.w);
}

// ============================================================
// FP16-in tensor-core GEMM NT: C[M,N] = A[M,K]*B[N,K]^T (+res)
// A,B fp16; C fp32 or fp16 (HOUT). Block 128x128, K-tile 32,
// 128 thr (4 warps 2Mx2N), warp tile 64x64. Double-buffered.
// ============================================================
template<int HOUT, bool RES>
__global__ __launch_bounds__(128, 2) void hgemm16(
    const __half* __restrict__ A, const __half* __restrict__ B,
    const float* __restrict__ Res, void* __restrict__ Cv,
    int M, int N, int K)
{
    __shared__ __align__(16) __half As[2][2][128][16];
    __shared__ __align__(16) __half Bs[2][2][128][16];

    const int tid  = threadIdx.x;
    const int lane = tid & 31;
    const int warp = tid >> 5;          // 0..3
    const int bm = blockIdx.y * 128;
    const int bn = blockIdx.x * 128;

    const int m0 = (warp & 1) * 64;
    const int n0 = (warp >> 1) * 64;

    // loader: 128 thr; A/B each 128 rows x 2 kk = 256 units -> 2 units/thread
    const int r_l  = tid >> 1;          // 0..63 (also +64)
    const int kk_l = tid & 1;
    const __half* Ag = A + (size_t)(bm + r_l) * K + kk_l * 16;
    const __half* Bg = B + (size_t)(bn + r_l) * K + kk_l * 16;
    const size_t rsk = (size_t)64 * K;

    float acc[4][8][4];
    #pragma unroll
    for (int i = 0; i < 4; i++)
        #pragma unroll
        for (int j = 0; j < 8; j++)
            acc[i][j][0] = acc[i][j][1] = acc[i][j][2] = acc[i][j][3] = 0.f;

    // preload tile 0
    {
        uint4 a00 = *reinterpret_cast<const uint4*>(Ag);
        uint4 a01 = *reinterpret_cast<const uint4*>(Ag + 8);
        uint4 a10 = *reinterpret_cast<const uint4*>(Ag + rsk);
        uint4 a11 = *reinterpret_cast<const uint4*>(Ag + rsk + 8);
        uint4 b00 = *reinterpret_cast<const uint4*>(Bg);
        uint4 b01 = *reinterpret_cast<const uint4*>(Bg + 8);
        uint4 b10 = *reinterpret_cast<const uint4*>(Bg + rsk);
        uint4 b11 = *reinterpret_cast<const uint4*>(Bg + rsk + 8);
        perm_sts(&As[0][kk_l][r_l     ][0], a00, a01);
        perm_sts(&As[0][kk_l][r_l + 64][0], a10, a11);
        perm_sts(&Bs[0][kk_l][r_l     ][0], b00, b01);
        perm_sts(&Bs[0][kk_l][r_l + 64][0], b10, b11);
    }
    __syncthreads();

    const int gr = lane >> 2;
    const int tq = lane & 3;
    const int KT = K >> 5;

    for (int kt = 0; kt < KT; ++kt) {
        const int buf = kt & 1;
        const bool pf = (kt + 1 < KT);
        uint4 pa0, pa1, pa2, pa3, pb0, pb1, pb2, pb3;
        if (pf) {
            const __half* Ap = Ag + (size_t)(kt + 1) * 32;
            const __half* Bp = Bg + (size_t)(kt + 1) * 32;
            pa0 = *reinterpret_cast<const uint4*>(Ap);
            pa1 = *reinterpret_cast<const uint4*>(Ap + 8);
            pa2 = *reinterpret_cast<const uint4*>(Ap + rsk);
            pa3 = *reinterpret_cast<const uint4*>(Ap + rsk + 8);
            pb0 = *reinterpret_cast<const uint4*>(Bp);
            pb1 = *reinterpret_cast<const uint4*>(Bp + 8);
            pb2 = *reinterpret_cast<const uint4*>(Bp + rsk);
            pb3 = *reinterpret_cast<const uint4*>(Bp + rsk + 8);
        }

        #pragma unroll
        for (int kk = 0; kk < 2; ++kk) {
            uint2 ax[4], ay[4];
            #pragma unroll
            for (int mi = 0; mi < 4; mi++) {
                const int r = m0 + mi * 16 + gr;
                ax[mi] = *reinterpret_cast<const uint2*>(&As[buf][kk][r    ][tq * 4]);
                ay[mi] = *reinterpret_cast<const uint2*>(&As[buf][kk][r + 8][tq * 4]);
            }
            #pragma unroll
            for (int ni = 0; ni < 8; ni++) {
                const uint2 bv = *reinterpret_cast<const uint2*>(&Bs[buf][kk][n0 + ni * 8 + gr][tq * 4]);
                #pragma unroll
                for (int mi = 0; mi < 4; mi++)
                    mma_f16(acc[mi][ni], ax[mi].x, ay[mi].x, ax[mi].y, ay[mi].y, bv.x, bv.y);
            }
        }

        if (pf) {
            const int nxt = buf ^ 1;
            perm_sts(&As[nxt][kk_l][r_l     ][0], pa0, pa1);
            perm_sts(&As[nxt][kk_l][r_l + 64][0], pa2, pa3);
            perm_sts(&Bs[nxt][kk_l][r_l     ][0], pb0, pb1);
            perm_sts(&Bs[nxt][kk_l][r_l + 64][0], pb2, pb3);
            __syncthreads();
        }
    }

    // epilogue
    const int gc = tq * 2;
    #pragma unroll
    for (int mi = 0; mi < 4; mi++) {
        #pragma unroll
        for (int ni = 0; ni < 8; ni++) {
            const int r = bm + m0 + mi * 16 + gr;
            const int c = bn + n0 + ni * 8 + gc;
            float2 lo = make_float2(acc[mi][ni][0], acc[mi][ni][1]);
            float2 hi = make_float2(acc[mi][ni][2], acc[mi][ni][3]);
            if (RES) {
                float2 rlo = *reinterpret_cast<const float2*>(Res + (size_t)r * N + c);
                float2 rhi = *reinterpret_cast<const float2*>(Res + (size_t)(r + 8) * N + c);
                lo.x += rlo.x; lo.y += rlo.y;
                hi.x += rhi.x; hi.y += rhi.y;
            }
            if (HOUT) {
                __half* C = (__half*)Cv;
                *reinterpret_cast<uint32_t*>(C + (size_t)r * N + c)       = packh2(lo.x, lo.y);
                *reinterpret_cast<uint32_t*>(C + (size_t)(r + 8) * N + c) = packh2(hi.x, hi.y);
            } else {
                float* C = (float*)Cv;
                *reinterpret_cast<float2*>(C + (size_t)r * N + c)       = lo;
                *reinterpret_cast<float2*>(C + (size_t)(r + 8) * N + c) = hi;
            }
        }
    }
}

// ============================================================
// RoPE + head reshape, fp16 in/out. q pre-scaled by 0.125.
// ============================================================
__global__ __launch_bounds__(256) void rope_reshape_kernel(
    const __half* __restrict__ qkv, const float* __restrict__ fc,
    __half* __restrict__ qr, __half* __restrict__ kr, __half* __restrict__ vr)
{
    const int gid = blockIdx.x * 256 + threadIdx.x;
    if (gid >= M_ * (QKVN/2)) return;
    const int row = gid / (QKVN/2);
    const int col = (gid - row * (QKVN/2)) * 2;
    const int b = row >> 11;
    const int s = row & (S_-1);
    const float2 xv = unpackh2(*reinterpret_cast<const uint32_t*>(qkv + (size_t)row * QKVN + col));
    const float x0 = xv.x, x1 = xv.y;

    if (col < E_) {
        const int hh = col >> 6, d = col & 63;
        const float c = fc[s*64 + d], sn = fc[s*64 + d + 1];
        *reinterpret_cast<uint32_t*>(qr + ((((size_t)b*H_ + hh) * S_ + s) << 6) + d) =
            packh2((x0*c - x1*sn) * 0.125f, (x1*c + x0*sn) * 0.125f);
    } else if (col < E_ + KV_) {
        const int kc = col - E_;
        const int kh = kc >> 6, d = kc & 63;
        const float c = fc[s*64 + d], sn = fc[s*64 + d + 1];
        *reinterpret_cast<uint32_t*>(kr + ((((size_t)b*KH_ + kh) * S_ + s) << 6) + d) =
            packh2(x0*c - x1*sn, x1*c + x0*sn);
    } else {
        const int vc = col - E_ - KV_;
        const int kh = vc >> 6, d = vc & 63;
        *reinterpret_cast<uint32_t*>(vr + ((((size_t)b*KH_ + kh) * S_ + s) << 6) + d) =
            packh2(x0, x1);
    }
}

// ============================================================
// Flash attention, fp16 mma, causal, GQA 4:1. fp16 output.
// ============================================================
__global__ __launch_bounds__(128) void attn_mma_kernel(
    const __half* __restrict__ qr, const __half* __restrict__ kr,
    const __half* __restrict__ vr, __half* __restrict__ of)
{
    __shared__ __align__(16) __half sQ[4][64][16];
    __shared__ __align__(16) __half sK[4][64][16];
    __shared__ __align__(16) __half sV[64][72];

    const int tid  = threadIdx.x;
    const int lane = tid & 31, warp = tid >> 5;
    const int qt = blockIdx.x, h = blockIdx.y, b = blockIdx.z;
    const int kvh = h >> 2;
    const __half* Q = qr + (((size_t)(b*H_ + h)) * S_ + qt*64) * HD_;
    const __half* K = kr + ((size_t)(b*KH_ + kvh)) * S_ * HD_;
    const __half* V = vr + ((size_t)(b*KH_ + kvh)) * S_ * HD_;

    #pragma unroll
    for (int it = 0; it < 4; it++) {
        const int f = tid + it*128;
        const int r = f >> 3, seg = f & 7;
        const int g = seg >> 1, hp = seg & 1;
        uint4 v4 = *reinterpret_cast<const uint4*>(Q + (size_t)r*64 + seg*8);
        uint32_t* p = reinterpret_cast<uint32_t*>(&sQ[g][r][0]);
        p[hp] = v4.x; p[hp+2] = v4.y; p[hp+4] = v4.z; p[hp+6] = v4.w;
    }

    const int gr = lane >> 2;
    const int tq = lane & 3;
    const int qrow = warp * 16;
    const int lm_r = (lane & 7) + ((lane >> 3) & 1) * 8;
    const int lm_c = ((lane >> 4) & 1) * 8;

    float m0 = -1e30f, m1 = -1e30f, l0 = 0.f, l1 = 0.f;
    float oac[8][4];
    #pragma unroll
    for (int i = 0; i < 8; i++)
        oac[i][0] = oac[i][1] = oac[i][2] = oac[i][3] = 0.f;

    for (int kt = 0; kt <= qt; ++kt) {
        __syncthreads();
        #pragma unroll
        for (int it = 0; it < 4; it++) {
            const int f = tid + it*128;
            const int r = f >> 3, seg = f & 7;
            const int g = seg >> 1, hp = seg & 1;
            uint4 kv4 = *reinterpret_cast<const uint4*>(K + ((size_t)kt*64 + r)*64 + seg*8);
            uint32_t* p = reinterpret_cast<uint32_t*>(&sK[g][r][0]);
            p[hp] = kv4.x; p[hp+2] = kv4.y; p[hp+4] = kv4.z; p[hp+6] = kv4.w;
            uint4 vv4 = *reinterpret_cast<const uint4*>(V + ((size_t)kt*64 + r)*64 + seg*8);
            *reinterpret_cast<uint4*>(&sV[r][seg*8]) = vv4;
        }
        __syncthreads();

        float sc[8][4];
        #pragma unroll
        for (int i = 0; i < 8; i++)
            sc[i][0] = sc[i][1] = sc[i][2] = sc[i][3] = 0.f;
        #pragma unroll
        for (int kk = 0; kk < 4; kk++) {
            const uint2 alo = *reinterpret_cast<const uint2*>(&sQ[kk][qrow + gr    ][tq*4]);
            const uint2 ahi = *reinterpret_cast<const uint2*>(&sQ[kk][qrow + gr + 8][tq*4]);
            #pragma unroll
            for (int ni = 0; ni < 8; ni++) {
                const uint2 bv = *reinterpret_cast<const uint2*>(&sK[kk][ni*8 + gr][tq*4]);
                mma_f16(sc[ni], alo.x, ahi.x, alo.y, ahi.y, bv.x, bv.y);
            }
        }

        if (kt == qt) {
            const int lr0 = qrow + gr, lr1 = lr0 + 8;
            #pragma unroll
            for (int ni = 0; ni < 8; ni++) {
                const int c0 = ni*8 + tq*2, c1 = c0 + 1;
                if (c0 > lr0) sc[ni][0] = -1e30f;
                if (c1 > lr0) sc[ni][1] = -1e30f;
                if (c0 > lr1) sc[ni][2] = -1e30f;
                if (c1 > lr1) sc[ni][3] = -1e30f;
            }
        }

        float mx0 = -1e30f, mx1 = -1e30f;
        #pragma unroll
        for (int ni = 0; ni < 8; ni++) {
            mx0 = fmaxf(mx0, fmaxf(sc[ni][0], sc[ni][1]));
            mx1 = fmaxf(mx1, fmaxf(sc[ni][2], sc[ni][3]));
        }
        mx0 = fmaxf(mx0, __shfl_xor_sync(0xffffffffu, mx0, 1));
        mx0 = fmaxf(mx0, __shfl_xor_sync(0xffffffffu, mx0, 2));
        mx1 = fmaxf(mx1, __shfl_xor_sync(0xffffffffu, mx1, 1));
        mx1 = fmaxf(mx1, __shfl_xor_sync(0xffffffffu, mx1, 2));
        const float nm0 = fmaxf(m0, mx0), nm1 = fmaxf(m1, mx1);
        const float al0 = __expf(m0 - nm0), al1 = __expf(m1 - nm1);
        m0 = nm0; m1 = nm1;

        float s0 = 0.f, s1 = 0.f;
        uint32_t pa[4][4];
        #pragma unroll
        for (int ni = 0; ni < 8; ni++) {
            const float p0 = __expf(sc[ni][0] - nm0);
            const float p1 = __expf(sc[ni][1] - nm0);
            const float p2 = __expf(sc[ni][2] - nm1);
            const float p3 = __expf(sc[ni][3] - nm1);
            s0 += p0 + p1; s1 += p2 + p3;
            const int kk = ni >> 1, w2 = (ni & 1) * 2;
            pa[kk][w2    ] = packh2(p0, p1);
            pa[kk][w2 + 1] = packh2(p2, p3);
        }
        s0 += __shfl_xor_sync(0xffffffffu, s0, 1);
        s0 += __shfl_xor_sync(0xffffffffu, s0, 2);
        s1 += __shfl_xor_sync(0xffffffffu, s1, 1);
        s1 += __shfl_xor_sync(0xffffffffu, s1, 2);
        l0 = l0 * al0 + s0;
        l1 = l1 * al1 + s1;
        #pragma unroll
        for (int ni = 0; ni < 8; ni++) {
            oac[ni][0] *= al0; oac[ni][1] *= al0;
            oac[ni][2] *= al1; oac[ni][3] *= al1;
        }

        #pragma unroll
        for (int kk = 0; kk < 4; kk++) {
            uint32_t bfr[8][2];
            #pragma unroll
            for (int nip = 0; nip < 4; nip++) {
                const uint32_t addr = smem_u32(&sV[16*kk + lm_r][nip*16 + lm_c]);
                asm volatile(
                    "ldmatrix.sync.aligned.m8n8.x4.trans.shared.b16 {%0,%1,%2,%3}, [%4];"
                    : "=r"(bfr[2*nip][0]), "=r"(bfr[2*nip][1]),
                      "=r"(bfr[2*nip+1][0]), "=r"(bfr[2*nip+1][1])
                    : "r"(addr));
            }
            #pragma unroll
            for (int ni = 0; ni < 8; ni++)
                mma_f16(oac[ni], pa[kk][0], pa[kk][1], pa[kk][2], pa[kk][3],
                        bfr[ni][0], bfr[ni][1]);
        }
    }

    const float il0 = 1.0f / l0, il1 = 1.0f / l1;
    const size_t row0 = (size_t)b * S_ + qt*64 + qrow + gr;
    __half* o0 = of + row0 * E_ + h*64;
    __half* o1 = o0 + (size_t)8 * E_;
    #pragma unroll
    for (int ni = 0; ni < 8; ni++) {
        *reinterpret_cast<uint32_t*>(o0 + ni*8 + tq*2) = packh2(oac[ni][0]*il0, oac[ni][1]*il0);
        *reinterpret_cast<uint32_t*>(o1 + ni*8 + tq*2) = packh2(oac[ni][2]*il1, oac[ni][3]*il1);
    }
}

// ============================================================
// SwiGLU from combined [gate|up] buffer (N=2F): act = silu(g)*u
// ============================================================
__global__ __launch_bounds__(256) void silu_mul_kernel(
    const __half* __restrict__ c13, __half* __restrict__ act)
{
    const size_t i = ((size_t)blockIdx.x * 256 + threadIdx.x) * 8;
    const size_t m = i >> 13;            // / F_
    const size_t f = i & (F_ - 1);
    const __half* gp = c13 + (m << 14) + f;       // m*2F + f
    const __half* up = gp + F_;
    uint4 gu = *reinterpret_cast<const uint4*>(gp);
    uint4 uu = *reinterpret_cast<const uint4*>(up);
    uint32_t go[4];
    const uint32_t* gw = &gu.x;
    const uint32_t* uw = &uu.x;
    #pragma unroll
    for (int j = 0; j < 4; j++) {
        float2 g2 = unpackh2(gw[j]);
        float2 u2 = unpackh2(uw[j]);
        g2.x = g2.x * u2.x / (1.f + __expf(-g2.x));
        g2.y = g2.y * u2.y / (1.f + __expf(-g2.y));
        go[j] = packh2(g2.x, g2.y);
    }
    *reinterpret_cast<uint4*>(act + i) = make_uint4(go[0], go[1], go[2], go[3]);
}

// ============================================================
// launch
// ============================================================
extern "C" void kernel_launch(void* const* d_in, const int* in_sizes, int n_in,
                              void* d_out, int out_size)
{
    (void)in_sizes; (void)n_in; (void)out_size;
    const float* x     = (const float*)d_in[0];
    const float* fc    = (const float*)d_in[2];
    const float* w_qkv = (const float*)d_in[3];
    const float* w_o   = (const float*)d_in[4];
    const float* w1    = (const float*)d_in[5];
    const float* w2    = (const float*)d_in[6];
    const float* w3    = (const float*)d_in[7];
    const float* anw   = (const float*)d_in[8];
    const float* fnw   = (const float*)d_in[9];
    float* out = (float*)d_out;

    __half *wqkvh, *woh, *w13h, *w2h;
    __half *h, *qkvh, *qh, *kh, *vh, *o, *g, *c13, *act;
    float  *h2;
    cudaGetSymbolAddress((void**)&wqkvh, g_wqkvh);
    cudaGetSymbolAddress((void**)&woh,   g_woh);
    cudaGetSymbolAddress((void**)&w13h,  g_w13h);
    cudaGetSymbolAddress((void**)&w2h,   g_w2h);
    cudaGetSymbolAddress((void**)&h,     g_h);
    cudaGetSymbolAddress((void**)&qkvh,  g_qkvh);
    cudaGetSymbolAddress((void**)&qh,    g_qh);
    cudaGetSymbolAddress((void**)&kh,    g_kh);
    cudaGetSymbolAddress((void**)&vh,    g_vh);
    cudaGetSymbolAddress((void**)&o,     g_o);
    cudaGetSymbolAddress((void**)&h2,    g_h2);
    cudaGetSymbolAddress((void**)&g,     g_g);
    cudaGetSymbolAddress((void**)&c13,   g_c13);
    cudaGetSymbolAddress((void**)&act,   g_act);

    // 0. weight conversion (fp32 -> fp16); w1|w3 concatenated
    f2h_kernel<<<(QKVN*E_)/1024, 256>>>(w_qkv, wqkvh);
    f2h_kernel<<<(E_*E_)/1024,   256>>>(w_o,   woh);
    f2h_kernel<<<(F_*E_)/1024,   256>>>(w1,    w13h);
    f2h_kernel<<<(F_*E_)/1024,   256>>>(w3,    w13h + (size_t)F_*E_);
    f2h_kernel<<<(E_*F_)/1024,   256>>>(w2,    w2h);

    // 1. attn rmsnorm -> fp16
    rmsnorm_kernel<<<M_, 256>>>(x, anw, h);
    // 2. qkv = h @ w_qkv^T -> fp16
    hgemm16<1,false><<<dim3(QKVN/128, M_/128), 128>>>(h, wqkvh, nullptr, qkvh, M_, QKVN, E_);
    // 3. rope + reshape (fp16 -> fp16)
    rope_reshape_kernel<<<(M_*(QKVN/2))/256, 256>>>(qkvh, fc, qh, kh, vh);
    // 4. attention -> fp16 o
    attn_mma_kernel<<<dim3(S_/64, H_, B_), 128>>>(qh, kh, vh, o);
    // 5. h2 = x + o @ w_o^T -> fp32
    hgemm16<0,true><<<dim3(E_/128, M_/128), 128>>>(o, woh, x, h2, M_, E_, E_);
    // 6. ffn rmsnorm -> fp16
    rmsnorm_kernel<<<M_, 256>>>(h2, fnw, g);
    // 7. [gate|up] = g @ [w1;w3]^T -> fp16 (one GEMM, N=2F)
    hgemm16<1,false><<<dim3((2*F_)/128, M_/128), 128>>>(g, w13h, nullptr, c13, M_, 2*F_, E_);
    // 8. swiglu
    silu_mul_kernel<<<((size_t)M_*F_/8)/256, 256>>>(c13, act);
    // 9. out = h2 + act @ w2^T -> fp32
    hgemm16<0,true><<<dim3(E_/128, M_/128), 128>>>(act, w2h, h2, out, M_, E_, F_);
}

// round 9
// speedup vs baseline: 1.0403x; 1.0403x over previous
#include <cuda_runtime.h>
#include <cuda_fp16.h>
#include <cstdint>

// Problem constants
#define B_    2
#define S_    2048
#define E_    2048
#define H_    32
#define KH_   8
#define HD_   64
#define F_    8192
#define KV_   (KH_*HD_)      // 512
#define QKVN  (E_ + 2*KV_)   // 3072
#define M_    (B_*S_)        // 4096

// -------- scratch (device globals: allocation-free) --------
__device__ __half g_wqkvh[(size_t)QKVN*E_];
__device__ __half g_woh  [(size_t)E_*E_];
__device__ __half g_w13h [(size_t)2*F_*E_];
__device__ __half g_w2h  [(size_t)E_*F_];

__device__ __half g_h    [(size_t)M_*E_];
__device__ __half g_qkvh [(size_t)M_*QKVN];
__device__ __half g_qh   [(size_t)B_*H_ *S_*HD_];
__device__ __half g_kh   [(size_t)B_*KH_*S_*HD_];
__device__ __half g_vh   [(size_t)B_*KH_*S_*HD_];
__device__ __half g_o    [(size_t)M_*E_];
__device__ float  g_h2   [(size_t)M_*E_];
__device__ __half g_g    [(size_t)M_*E_];
__device__ __half g_c13  [(size_t)M_*2*F_];
__device__ __half g_act  [(size_t)M_*F_];

__device__ __forceinline__ uint32_t smem_u32(const void* p) {
    uint32_t a;
    asm("{ .reg .u64 t; cvta.to.shared.u64 t, %1; cvt.u32.u64 %0, t; }" : "=r"(a) : "l"(p));
    return a;
}
__device__ __forceinline__ uint32_t packh2(float a, float b) {
    __half2 h = __floats2half2_rn(a, b);
    return *reinterpret_cast<uint32_t*>(&h);
}
__device__ __forceinline__ float2 unpackh2(uint32_t u) {
    __half2 h = *reinterpret_cast<__half2*>(&u);
    return __half22float2(h);
}

// ============================================================
// fp32 -> fp16 bulk convert (weights). n % 1024 == 0.
// ============================================================
__global__ __launch_bounds__(256) void f2h_kernel(
    const float* __restrict__ in, __half* __restrict__ out)
{
    const size_t i = ((size_t)blockIdx.x * 256 + threadIdx.x) * 4;
    float4 v = *reinterpret_cast<const float4*>(in + i);
    uint2 o = make_uint2(packh2(v.x, v.y), packh2(v.z, v.w));
    *reinterpret_cast<uint2*>(out + i) = o;
}

// ============================================================
// RMSNorm: fp32 in, fp16 out. one block per row of 2048
// ============================================================
__global__ __launch_bounds__(256) void rmsnorm_kernel(
    const float* __restrict__ x, const float* __restrict__ w, __half* __restrict__ o)
{
    const int tid = threadIdx.x;
    const size_t base = (size_t)blockIdx.x * E_;
    float4 v0 = *reinterpret_cast<const float4*>(x + base + tid*4);
    float4 v1 = *reinterpret_cast<const float4*>(x + base + 1024 + tid*4);
    float ss = v0.x*v0.x + v0.y*v0.y + v0.z*v0.z + v0.w*v0.w
             + v1.x*v1.x + v1.y*v1.y + v1.z*v1.z + v1.w*v1.w;
    #pragma unroll
    for (int off = 16; off; off >>= 1) ss += __shfl_xor_sync(0xffffffffu, ss, off);
    __shared__ float sred[8];
    if ((tid & 31) == 0) sred[tid >> 5] = ss;
    __syncthreads();
    float tot = 0.f;
    #pragma unroll
    for (int i = 0; i < 8; i++) tot += sred[i];
    float inv = rsqrtf(tot * (1.0f / (float)E_) + 1e-5f);
    float4 w0 = *reinterpret_cast<const float4*>(w + tid*4);
    float4 w1 = *reinterpret_cast<const float4*>(w + 1024 + tid*4);
    uint2 o0 = make_uint2(packh2(v0.x*inv*w0.x, v0.y*inv*w0.y),
                          packh2(v0.z*inv*w0.z, v0.w*inv*w0.w));
    uint2 o1 = make_uint2(packh2(v1.x*inv*w1.x, v1.y*inv*w1.y),
                          packh2(v1.z*inv*w1.z, v1.w*inv*w1.w));
    *reinterpret_cast<uint2*>(o + base + tid*4)        = o0;
    *reinterpret_cast<uint2*>(o + base + 1024 + tid*4) = o1;
}

// -------- fp16 mma --------
__device__ __forceinline__ void mma_f16(float* c,
    uint32_t a0, uint32_t a1, uint32_t a2, uint32_t a3,
    uint32_t b0, uint32_t b1)
{
    asm volatile(
        "mma.sync.aligned.m16n8k16.row.col.f32.f16.f16.f32 "
        "{%0,%1,%2,%3}, {%4,%5,%6,%7}, {%8,%9}, {%0,%1,%2,%3};"
        : "+f"(c[0]), "+f"(c[1]), "+f"(c[2]), "+f"(c[3])
        : "r"(a0), "r"(a1), "r"(a2), "r"(a3), "r"(b0), "r"(b1));
}

// interleave two uint4 (halves k0..7, k8..15) into perm slot order
__device__ __forceinline__ void perm_sts(__half* rowp, uint4 lo, uint4 hi) {
    *reinterpret_cast<uint4*>(rowp)     = make_uint4(lo.x, hi.x, lo.y, hi.y);
    *reinterpret_cast<uint4*>(rowp + 8) = make_uint4(lo.z, hi.z, lo.w, hi.w);
}

// ============================================================
// FP16-in tensor-core GEMM NT (R7 proven config):
// Block 128x128, K-tile 32, 256 thr (8 warps 4Mx2N), warp 32x64.
// ============================================================
template<int HOUT, bool RES>
__global__ __launch_bounds__(256, 2) void hgemm16(
    const __half* __restrict__ A, const __half* __restrict__ B,
    const float* __restrict__ Res, void* __restrict__ Cv,
    int M, int N, int K)
{
    __shared__ __align__(16) __half As[2][2][128][16];
    __shared__ __align__(16) __half Bs[2][2][128][16];

    const int tid  = threadIdx.x;
    const int lane = tid & 31;
    const int warp = tid >> 5;
    const int bm = blockIdx.y * 128;
    const int bn = blockIdx.x * 128;

    const int m0 = (warp & 3) * 32;
    const int n0 = (warp >> 2) * 64;

    const int r_l  = tid >> 1;    // 0..127
    const int kk_l = tid & 1;     // 0..1
    const __half* Ag = A + (size_t)(bm + r_l) * K + kk_l * 16;
    const __half* Bg = B + (size_t)(bn + r_l) * K + kk_l * 16;

    float acc[2][8][4];
    #pragma unroll
    for (int i = 0; i < 2; i++)
        #pragma unroll
        for (int j = 0; j < 8; j++)
            acc[i][j][0] = acc[i][j][1] = acc[i][j][2] = acc[i][j][3] = 0.f;

    {
        uint4 a0 = *reinterpret_cast<const uint4*>(Ag);
        uint4 a1 = *reinterpret_cast<const uint4*>(Ag + 8);
        uint4 b0 = *reinterpret_cast<const uint4*>(Bg);
        uint4 b1 = *reinterpret_cast<const uint4*>(Bg + 8);
        perm_sts(&As[0][kk_l][r_l][0], a0, a1);
        perm_sts(&Bs[0][kk_l][r_l][0], b0, b1);
    }
    __syncthreads();

    const int gr = lane >> 2;
    const int tq = lane & 3;
    const int KT = K >> 5;

    for (int kt = 0; kt < KT; ++kt) {
        const int buf = kt & 1;
        const bool pf = (kt + 1 < KT);
        uint4 pa0, pa1, pb0, pb1;
        if (pf) {
            const __half* Ap = Ag + (size_t)(kt + 1) * 32;
            const __half* Bp = Bg + (size_t)(kt + 1) * 32;
            pa0 = *reinterpret_cast<const uint4*>(Ap);
            pa1 = *reinterpret_cast<const uint4*>(Ap + 8);
            pb0 = *reinterpret_cast<const uint4*>(Bp);
            pb1 = *reinterpret_cast<const uint4*>(Bp + 8);
        }

        #pragma unroll
        for (int kk = 0; kk < 2; ++kk) {
            uint2 ax[2], ay[2];
            #pragma unroll
            for (int mi = 0; mi < 2; mi++) {
                const int r = m0 + mi * 16 + gr;
                ax[mi] = *reinterpret_cast<const uint2*>(&As[buf][kk][r    ][tq * 4]);
                ay[mi] = *reinterpret_cast<const uint2*>(&As[buf][kk][r + 8][tq * 4]);
            }
            #pragma unroll
            for (int ni = 0; ni < 8; ni++) {
                const uint2 bv = *reinterpret_cast<const uint2*>(&Bs[buf][kk][n0 + ni * 8 + gr][tq * 4]);
                #pragma unroll
                for (int mi = 0; mi < 2; mi++)
                    mma_f16(acc[mi][ni], ax[mi].x, ay[mi].x, ax[mi].y, ay[mi].y, bv.x, bv.y);
            }
        }

        if (pf) {
            const int nxt = buf ^ 1;
            perm_sts(&As[nxt][kk_l][r_l][0], pa0, pa1);
            perm_sts(&Bs[nxt][kk_l][r_l][0], pb0, pb1);
            __syncthreads();
        }
    }

    const int gc = tq * 2;
    #pragma unroll
    for (int mi = 0; mi < 2; mi++) {
        #pragma unroll
        for (int ni = 0; ni < 8; ni++) {
            const int r = bm + m0 + mi * 16 + gr;
            const int c = bn + n0 + ni * 8 + gc;
            float2 lo = make_float2(acc[mi][ni][0], acc[mi][ni][1]);
            float2 hi = make_float2(acc[mi][ni][2], acc[mi][ni][3]);
            if (RES) {
                float2 rlo = *reinterpret_cast<const float2*>(Res + (size_t)r * N + c);
                float2 rhi = *reinterpret_cast<const float2*>(Res + (size_t)(r + 8) * N + c);
                lo.x += rlo.x; lo.y += rlo.y;
                hi.x += rhi.x; hi.y += rhi.y;
            }
            if (HOUT) {
                __half* C = (__half*)Cv;
                *reinterpret_cast<uint32_t*>(C + (size_t)r * N + c)       = packh2(lo.x, lo.y);
                *reinterpret_cast<uint32_t*>(C + (size_t)(r + 8) * N + c) = packh2(hi.x, hi.y);
            } else {
                float* C = (float*)Cv;
                *reinterpret_cast<float2*>(C + (size_t)r * N + c)       = lo;
                *reinterpret_cast<float2*>(C + (size_t)(r + 8) * N + c) = hi;
            }
        }
    }
}

// ============================================================
// RoPE + head reshape, fp16 in/out. q pre-scaled by 0.125.
// ============================================================
__global__ __launch_bounds__(256) void rope_reshape_kernel(
    const __half* __restrict__ qkv, const float* __restrict__ fc,
    __half* __restrict__ qr, __half* __restrict__ kr, __half* __restrict__ vr)
{
    const int gid = blockIdx.x * 256 + threadIdx.x;
    if (gid >= M_ * (QKVN/2)) return;
    const int row = gid / (QKVN/2);
    const int col = (gid - row * (QKVN/2)) * 2;
    const int b = row >> 11;
    const int s = row & (S_-1);
    const float2 xv = unpackh2(*reinterpret_cast<const uint32_t*>(qkv + (size_t)row * QKVN + col));
    const float x0 = xv.x, x1 = xv.y;

    if (col < E_) {
        const int hh = col >> 6, d = col & 63;
        const float c = fc[s*64 + d], sn = fc[s*64 + d + 1];
        *reinterpret_cast<uint32_t*>(qr + ((((size_t)b*H_ + hh) * S_ + s) << 6) + d) =
            packh2((x0*c - x1*sn) * 0.125f, (x1*c + x0*sn) * 0.125f);
    } else if (col < E_ + KV_) {
        const int kc = col - E_;
        const int kh = kc >> 6, d = kc & 63;
        const float c = fc[s*64 + d], sn = fc[s*64 + d + 1];
        *reinterpret_cast<uint32_t*>(kr + ((((size_t)b*KH_ + kh) * S_ + s) << 6) + d) =
            packh2(x0*c - x1*sn, x1*c + x0*sn);
    } else {
        const int vc = col - E_ - KV_;
        const int kh = vc >> 6, d = vc & 63;
        *reinterpret_cast<uint32_t*>(vr + ((((size_t)b*KH_ + kh) * S_ + s) << 6) + d) =
            packh2(x0, x1);
    }
}

// ============================================================
// Flash attention, fp16 mma, causal, GQA 4:1. fp16 output.
// 128 q-rows x 64 k-cols per block, 256 thr (8 warps x 16 rows).
// ============================================================
__global__ __launch_bounds__(256) void attn_mma_kernel(
    const __half* __restrict__ qr, const __half* __restrict__ kr,
    const __half* __restrict__ vr, __half* __restrict__ of)
{
    __shared__ __align__(16) __half sQ[4][128][16];
    __shared__ __align__(16) __half sK[4][64][16];
    __shared__ __align__(16) __half sV[64][72];

    const int tid  = threadIdx.x;
    const int lane = tid & 31, warp = tid >> 5;
    const int qt = blockIdx.x, h = blockIdx.y, b = blockIdx.z;
    const int kvh = h >> 2;
    const __half* Q = qr + (((size_t)(b*H_ + h)) * S_ + qt*128) * HD_;
    const __half* K = kr + ((size_t)(b*KH_ + kvh)) * S_ * HD_;
    const __half* V = vr + ((size_t)(b*KH_ + kvh)) * S_ * HD_;

    // load Q tile (128 rows x 8 segs = 1024 units; 256 thr x 4)
    #pragma unroll
    for (int it = 0; it < 4; it++) {
        const int f = tid + it*256;
        const int r = f >> 3, seg = f & 7;
        const int g = seg >> 1, hp = seg & 1;
        uint4 v4 = *reinterpret_cast<const uint4*>(Q + (size_t)r*64 + seg*8);
        uint32_t* p = reinterpret_cast<uint32_t*>(&sQ[g][r][0]);
        p[hp] = v4.x; p[hp+2] = v4.y; p[hp+4] = v4.z; p[hp+6] = v4.w;
    }

    const int gr = lane >> 2;
    const int tq = lane & 3;
    const int qrow = warp * 16;
    const int lm_r = (lane & 7) + ((lane >> 3) & 1) * 8;
    const int lm_c = ((lane >> 4) & 1) * 8;

    float m0 = -1e30f, m1 = -1e30f, l0 = 0.f, l1 = 0.f;
    float oac[8][4];
    #pragma unroll
    for (int i = 0; i < 8; i++)
        oac[i][0] = oac[i][1] = oac[i][2] = oac[i][3] = 0.f;

    const int KTILES = 2*qt + 2;     // k range [0, qt*128+128)
    for (int kt = 0; kt < KTILES; ++kt) {
        __syncthreads();
        // load K/V tile (64 rows x 8 segs = 512 units; 256 thr x 2)
        #pragma unroll
        for (int it = 0; it < 2; it++) {
            const int f = tid + it*256;
            const int r = f >> 3, seg = f & 7;
            const int g = seg >> 1, hp = seg & 1;
            uint4 kv4 = *reinterpret_cast<const uint4*>(K + ((size_t)kt*64 + r)*64 + seg*8);
            uint32_t* p = reinterpret_cast<uint32_t*>(&sK[g][r][0]);
            p[hp] = kv4.x; p[hp+2] = kv4.y; p[hp+4] = kv4.z; p[hp+6] = kv4.w;
            uint4 vv4 = *reinterpret_cast<const uint4*>(V + ((size_t)kt*64 + r)*64 + seg*8);
            *reinterpret_cast<uint4*>(&sV[r][seg*8]) = vv4;
        }
        __syncthreads();

        float sc[8][4];
        #pragma unroll
        for (int i = 0; i < 8; i++)
            sc[i][0] = sc[i][1] = sc[i][2] = sc[i][3] = 0.f;
        #pragma unroll
        for (int kk = 0; kk < 4; kk++) {
            const uint2 alo = *reinterpret_cast<const uint2*>(&sQ[kk][qrow + gr    ][tq*4]);
            const uint2 ahi = *reinterpret_cast<const uint2*>(&sQ[kk][qrow + gr + 8][tq*4]);
            #pragma unroll
            for (int ni = 0; ni < 8; ni++) {
                const uint2 bv = *reinterpret_cast<const uint2*>(&sK[kk][ni*8 + gr][tq*4]);
                mma_f16(sc[ni], alo.x, ahi.x, alo.y, ahi.y, bv.x, bv.y);
            }
        }

        // causal mask (global indices) on the two possibly-diagonal tiles
        if (kt >= 2*qt) {
            const int r0g = qt*128 + qrow + gr;
            const int r1g = r0g + 8;
            #pragma unroll
            for (int ni = 0; ni < 8; ni++) {
                const int c0 = kt*64 + ni*8 + tq*2, c1 = c0 + 1;
                if (c0 > r0g) sc[ni][0] = -1e30f;
                if (c1 > r0g) sc[ni][1] = -1e30f;
                if (c0 > r1g) sc[ni][2] = -1e30f;
                if (c1 > r1g) sc[ni][3] = -1e30f;
            }
        }

        float mx0 = -1e30f, mx1 = -1e30f;
        #pragma unroll
        for (int ni = 0; ni < 8; ni++) {
            mx0 = fmaxf(mx0, fmaxf(sc[ni][0], sc[ni][1]));
            mx1 = fmaxf(mx1, fmaxf(sc[ni][2], sc[ni][3]));
        }
        mx0 = fmaxf(mx0, __shfl_xor_sync(0xffffffffu, mx0, 1));
        mx0 = fmaxf(mx0, __shfl_xor_sync(0xffffffffu, mx0, 2));
        mx1 = fmaxf(mx1, __shfl_xor_sync(0xffffffffu, mx1, 1));
        mx1 = fmaxf(mx1, __shfl_xor_sync(0xffffffffu, mx1, 2));
        const float nm0 = fmaxf(m0, mx0), nm1 = fmaxf(m1, mx1);
        const float al0 = __expf(m0 - nm0), al1 = __expf(m1 - nm1);
        m0 = nm0; m1 = nm1;

        float s0 = 0.f, s1 = 0.f;
        uint32_t pa[4][4];
        #pragma unroll
        for (int ni = 0; ni < 8; ni++) {
            const float p0 = __expf(sc[ni][0] - nm0);
            const float p1 = __expf(sc[ni][1] - nm0);
            const float p2 = __expf(sc[ni][2] - nm1);
            const float p3 = __expf(sc[ni][3] - nm1);
            s0 += p0 + p1; s1 += p2 + p3;
            const int kk = ni >> 1, w2 = (ni & 1) * 2;
            pa[kk][w2    ] = packh2(p0, p1);
            pa[kk][w2 + 1] = packh2(p2, p3);
        }
        s0 += __shfl_xor_sync(0xffffffffu, s0, 1);
        s0 += __shfl_xor_sync(0xffffffffu, s0, 2);
        s1 += __shfl_xor_sync(0xffffffffu, s1, 1);
        s1 += __shfl_xor_sync(0xffffffffu, s1, 2);
        l0 = l0 * al0 + s0;
        l1 = l1 * al1 + s1;
        #pragma unroll
        for (int ni = 0; ni < 8; ni++) {
            oac[ni][0] *= al0; oac[ni][1] *= al0;
            oac[ni][2] *= al1; oac[ni][3] *= al1;
        }

        #pragma unroll
        for (int kk = 0; kk < 4; kk++) {
            uint32_t bfr[8][2];
            #pragma unroll
            for (int nip = 0; nip < 4; nip++) {
                const uint32_t addr = smem_u32(&sV[16*kk + lm_r][nip*16 + lm_c]);
                asm volatile(
                    "ldmatrix.sync.aligned.m8n8.x4.trans.shared.b16 {%0,%1,%2,%3}, [%4];"
                    : "=r"(bfr[2*nip][0]), "=r"(bfr[2*nip][1]),
                      "=r"(bfr[2*nip+1][0]), "=r"(bfr[2*nip+1][1])
                    : "r"(addr));
            }
            #pragma unroll
            for (int ni = 0; ni < 8; ni++)
                mma_f16(oac[ni], pa[kk][0], pa[kk][1], pa[kk][2], pa[kk][3],
                        bfr[ni][0], bfr[ni][1]);
        }
    }

    const float il0 = 1.0f / l0, il1 = 1.0f / l1;
    const size_t row0 = (size_t)b * S_ + qt*128 + qrow + gr;
    __half* o0 = of + row0 * E_ + h*64;
    __half* o1 = o0 + (size_t)8 * E_;
    #pragma unroll
    for (int ni = 0; ni < 8; ni++) {
        *reinterpret_cast<uint32_t*>(o0 + ni*8 + tq*2) = packh2(oac[ni][0]*il0, oac[ni][1]*il0);
        *reinterpret_cast<uint32_t*>(o1 + ni*8 + tq*2) = packh2(oac[ni][2]*il1, oac[ni][3]*il1);
    }
}

// ============================================================
// SwiGLU from combined [gate|up] buffer (N=2F): act = silu(g)*u
// ============================================================
__global__ __launch_bounds__(256) void silu_mul_kernel(
    const __half* __restrict__ c13, __half* __restrict__ act)
{
    const size_t i = ((size_t)blockIdx.x * 256 + threadIdx.x) * 8;
    const size_t m = i >> 13;            // / F_
    const size_t f = i & (F_ - 1);
    const __half* gp = c13 + (m << 14) + f;       // m*2F + f
    const __half* up = gp + F_;
    uint4 gu = *reinterpret_cast<const uint4*>(gp);
    uint4 uu = *reinterpret_cast<const uint4*>(up);
    uint32_t go[4];
    const uint32_t* gw = &gu.x;
    const uint32_t* uw = &uu.x;
    #pragma unroll
    for (int j = 0; j < 4; j++) {
        float2 g2 = unpackh2(gw[j]);
        float2 u2 = unpackh2(uw[j]);
        g2.x = g2.x * u2.x / (1.f + __expf(-g2.x));
        g2.y = g2.y * u2.y / (1.f + __expf(-g2.y));
        go[j] = packh2(g2.x, g2.y);
    }
    *reinterpret_cast<uint4*>(act + i) = make_uint4(go[0], go[1], go[2], go[3]);
}

// ============================================================
// launch
// ============================================================
extern "C" void kernel_launch(void* const* d_in, const int* in_sizes, int n_in,
                              void* d_out, int out_size)
{
    (void)in_sizes; (void)n_in; (void)out_size;
    const float* x     = (const float*)d_in[0];
    const float* fc    = (const float*)d_in[2];
    const float* w_qkv = (const float*)d_in[3];
    const float* w_o   = (const float*)d_in[4];
    const float* w1    = (const float*)d_in[5];
    const float* w2    = (const float*)d_in[6];
    const float* w3    = (const float*)d_in[7];
    const float* anw   = (const float*)d_in[8];
    const float* fnw   = (const float*)d_in[9];
    float* out = (float*)d_out;

    __half *wqkvh, *woh, *w13h, *w2h;
    __half *h, *qkvh, *qh, *kh, *vh, *o, *g, *c13, *act;
    float  *h2;
    cudaGetSymbolAddress((void**)&wqkvh, g_wqkvh);
    cudaGetSymbolAddress((void**)&woh,   g_woh);
    cudaGetSymbolAddress((void**)&w13h,  g_w13h);
    cudaGetSymbolAddress((void**)&w2h,   g_w2h);
    cudaGetSymbolAddress((void**)&h,     g_h);
    cudaGetSymbolAddress((void**)&qkvh,  g_qkvh);
    cudaGetSymbolAddress((void**)&qh,    g_qh);
    cudaGetSymbolAddress((void**)&kh,    g_kh);
    cudaGetSymbolAddress((void**)&vh,    g_vh);
    cudaGetSymbolAddress((void**)&o,     g_o);
    cudaGetSymbolAddress((void**)&h2,    g_h2);
    cudaGetSymbolAddress((void**)&g,     g_g);
    cudaGetSymbolAddress((void**)&c13,   g_c13);
    cudaGetSymbolAddress((void**)&act,   g_act);

    // 0. weight conversion (fp32 -> fp16); w1|w3 concatenated
    f2h_kernel<<<(QKVN*E_)/1024, 256>>>(w_qkv, wqkvh);
    f2h_kernel<<<(E_*E_)/1024,   256>>>(w_o,   woh);
    f2h_kernel<<<(F_*E_)/1024,   256>>>(w1,    w13h);
    f2h_kernel<<<(F_*E_)/1024,   256>>>(w3,    w13h + (size_t)F_*E_);
    f2h_kernel<<<(E_*F_)/1024,   256>>>(w2,    w2h);

    // 1. attn rmsnorm -> fp16
    rmsnorm_kernel<<<M_, 256>>>(x, anw, h);
    // 2. qkv = h @ w_qkv^T -> fp16
    hgemm16<1,false><<<dim3(QKVN/128, M_/128), 256>>>(h, wqkvh, nullptr, qkvh, M_, QKVN, E_);
    // 3. rope + reshape (fp16 -> fp16)
    rope_reshape_kernel<<<(M_*(QKVN/2))/256, 256>>>(qkvh, fc, qh, kh, vh);
    // 4. attention -> fp16 o (128-row Q tiles)
    attn_mma_kernel<<<dim3(S_/128, H_, B_), 256>>>(qh, kh, vh, o);
    // 5. h2 = x + o @ w_o^T -> fp32
    hgemm16<0,true><<<dim3(E_/128, M_/128), 256>>>(o, woh, x, h2, M_, E_, E_);
    // 6. ffn rmsnorm -> fp16
    rmsnorm_kernel<<<M_, 256>>>(h2, fnw, g);
    // 7. [gate|up] = g @ [w1;w3]^T -> fp16 (one GEMM, N=2F)
    hgemm16<1,false><<<dim3((2*F_)/128, M_/128), 256>>>(g, w13h, nullptr, c13, M_, 2*F_, E_);
    // 8. swiglu
    silu_mul_kernel<<<((size_t)M_*F_/8)/256, 256>>>(c13, act);
    // 9. out = h2 + act @ w2^T -> fp32
    hgemm16<0,true><<<dim3(E_/128, M_/128), 256>>>(act, w2h, h2, out, M_, E_, F_);
}